// round 3
// baseline (speedup 1.0000x reference)
#include <cuda_runtime.h>

#define NW 12
#define DIM 4096        // 2^12
#define INDIM 256
#define DEPTH 4
#define NT 256

// XOR swizzle so all three phase layouts are bank-conflict-free
__device__ __forceinline__ int slot(int i) { return i ^ ((i >> 4) & 0xF); }

// RX pair update: b0 = c*a0 - i s a1 ; b1 = -i s a0 + c*a1
__device__ __forceinline__ void rx_pair(float2& a0, float2& a1, float c, float s) {
    float b0x = fmaf(c, a0.x,  s * a1.y);
    float b0y = fmaf(c, a0.y, -s * a1.x);
    float b1x = fmaf(c, a1.x,  s * a0.y);
    float b1y = fmaf(c, a1.y, -s * a0.x);
    a0.x = b0x; a0.y = b0y; a1.x = b1x; a1.y = b1y;
}

// Apply 4 RX butterflies on the 4 local bits of A[16]
__device__ __forceinline__ void apply4(float2 A[16], const float ck[4], const float sk[4]) {
#pragma unroll
    for (int k = 0; k < 4; k++) {
        const int m = 1 << k;
#pragma unroll
        for (int i0 = 0; i0 < 16; i0++)
            if (!(i0 & m)) rx_pair(A[i0], A[i0 | m], ck[k], sk[k]);
    }
}

__global__ void __launch_bounds__(NT)
sim_kernel(const float* __restrict__ x, const float* __restrict__ W,
           const float* __restrict__ params, float* __restrict__ out)
{
    __shared__ float2 st[DIM];              // 32 KB state
    __shared__ float ic[NW], isn[NW];       // initial layer cos/sin of half-angle
    __shared__ float pc[DEPTH * NW], ps[DEPTH * NW];
    __shared__ float red[NW * 8];
    __shared__ float osum[NW * 8];

    const int tid  = threadIdx.x;
    const int b    = blockIdx.x;
    const int lane = tid & 31;
    const int warp = tid >> 5;

    // ---- angles[b,w] = dot(x[b,:], W[w,:]) ; one element per thread ----
    float xv = x[b * INDIM + tid];
#pragma unroll
    for (int w = 0; w < NW; w++) {
        float p = xv * __ldg(&W[w * INDIM + tid]);
#pragma unroll
        for (int o = 16; o > 0; o >>= 1) p += __shfl_xor_sync(0xffffffffu, p, o);
        if (lane == 0) red[w * 8 + warp] = p;
    }
    __syncthreads();
    if (tid < NW) {
        float a = 0.f;
#pragma unroll
        for (int k = 0; k < 8; k++) a += red[tid * 8 + k];
        float sv, cv; sincosf(a * 0.5f, &sv, &cv);
        ic[tid] = cv; isn[tid] = sv;
    }
    if (tid < DEPTH * NW) {
        float sv, cv; sincosf(params[tid] * 0.5f, &sv, &cv);
        pc[tid] = cv; ps[tid] = sv;
    }
    __syncthreads();

    // ---- construct product state directly (absorbs the whole initial RX layer)
    // hi layout: index j = (g<<8) | tid ; index bit b <-> wire (11-b)
    float2 A[16];
    {
        float base = 1.f;
#pragma unroll
        for (int bb = 0; bb < 8; bb++) {
            int bit = (tid >> bb) & 1;
            base *= bit ? isn[11 - bb] : ic[11 - bb];
        }
        int bcnt = __popc(tid);
#pragma unroll
        for (int g = 0; g < 16; g++) {
            float pr = base;
#pragma unroll
            for (int bb = 0; bb < 4; bb++) {
                int bit = (g >> bb) & 1;
                pr *= bit ? isn[3 - bb] : ic[3 - bb];
            }
            int c = (bcnt + __popc(g)) & 3;   // amp = pr * (-i)^c
            float2 a;
            a.x = (c == 0) ? pr : ((c == 2) ? -pr : 0.f);
            a.y = (c == 1) ? -pr : ((c == 3) ? pr : 0.f);
            A[g] = a;
        }
    }

    const int mid_base = ((tid >> 4) << 8) | (tid & 15);

    // ---- depth 0 ----
    {
        float ck[4], sk[4];
#pragma unroll
        for (int k = 0; k < 4; k++) { ck[k] = pc[3 - k];  sk[k] = ps[3 - k]; }   // wires 0..3 (bits 8+k of j)
        apply4(A, ck, sk);
#pragma unroll
        for (int g = 0; g < 16; g++) st[slot((g << 8) | tid)] = A[g];
    }
    __syncthreads();
    {   // mid: local bit k <-> wire 7-k
#pragma unroll
        for (int g = 0; g < 16; g++) A[g] = st[slot(mid_base | (g << 4))];
        float ck[4], sk[4];
#pragma unroll
        for (int k = 0; k < 4; k++) { ck[k] = pc[7 - k];  sk[k] = ps[7 - k]; }
        apply4(A, ck, sk);
#pragma unroll
        for (int g = 0; g < 16; g++) st[slot(mid_base | (g << 4))] = A[g];
    }
    __syncthreads();
    {   // lo: local bit k <-> wire 11-k
#pragma unroll
        for (int g = 0; g < 16; g++) A[g] = st[slot((tid << 4) | g)];
        float ck[4], sk[4];
#pragma unroll
        for (int k = 0; k < 4; k++) { ck[k] = pc[11 - k]; sk[k] = ps[11 - k]; }
        apply4(A, ck, sk);
#pragma unroll
        for (int g = 0; g < 16; g++) st[slot((tid << 4) | g)] = A[g];
    }
    __syncthreads();

    // ---- depths 1..3 : CNOT-chain permutation fused into the hi-phase read ----
    for (int d = 1; d < DEPTH; d++) {
        const float* pcd = pc + d * NW;
        const float* psd = ps + d * NW;
        // hi phase: read permuted  new[j] = old[j ^ (j>>1)]
#pragma unroll
        for (int g = 0; g < 16; g++) {
            int j = (g << 8) | tid;
            A[g] = st[slot(j ^ (j >> 1))];
        }
        __syncthreads();   // all reads before any write (perm crosses ownership)
        {
            float ck[4], sk[4];
#pragma unroll
            for (int k = 0; k < 4; k++) { ck[k] = pcd[3 - k]; sk[k] = psd[3 - k]; }
            apply4(A, ck, sk);
        }
#pragma unroll
        for (int g = 0; g < 16; g++) st[slot((g << 8) | tid)] = A[g];
        __syncthreads();
        // mid phase
#pragma unroll
        for (int g = 0; g < 16; g++) A[g] = st[slot(mid_base | (g << 4))];
        {
            float ck[4], sk[4];
#pragma unroll
            for (int k = 0; k < 4; k++) { ck[k] = pcd[7 - k]; sk[k] = psd[7 - k]; }
            apply4(A, ck, sk);
        }
#pragma unroll
        for (int g = 0; g < 16; g++) st[slot(mid_base | (g << 4))] = A[g];
        __syncthreads();
        // lo phase
#pragma unroll
        for (int g = 0; g < 16; g++) A[g] = st[slot((tid << 4) | g)];
        {
            float ck[4], sk[4];
#pragma unroll
            for (int k = 0; k < 4; k++) { ck[k] = pcd[11 - k]; sk[k] = psd[11 - k]; }
            apply4(A, ck, sk);
        }
        // d == DEPTH-1: amplitudes stay in registers for measurement
        if (d < DEPTH - 1) {
#pragma unroll
            for (int g = 0; g < 16; g++) st[slot((tid << 4) | g)] = A[g];
            __syncthreads();
        }
    }

    // ---- per-wire measurement with final CNOT perm absorbed:
    // measured state F[m] = S[m ^ (m>>1)]  =>  with j = gray(m):
    // out[w] = sum_j (1 - 2*parity(popc(j >> (11-w)))) * |S_j|^2
    float acc[NW];
#pragma unroll
    for (int w = 0; w < NW; w++) acc[w] = 0.f;

#pragma unroll
    for (int g = 0; g < 16; g++) {
        int j = (tid << 4) | g;
        float p = A[g].x * A[g].x + A[g].y * A[g].y;
        int par = 0;                 // parity of popc(j >> b), running from b=11 down
#pragma unroll
        for (int bb = 11; bb >= 0; bb--) {
            par ^= (j >> bb) & 1;    // now par = parity(popc(j >> bb))
            int w = 11 - bb;         // wire measured on bit bb
            acc[w] += par ? -p : p;
        }
    }
#pragma unroll
    for (int w = 0; w < NW; w++) {
        float v = acc[w];
#pragma unroll
        for (int o = 16; o > 0; o >>= 1) v += __shfl_xor_sync(0xffffffffu, v, o);
        if (lane == 0) osum[w * 8 + warp] = v;
    }
    __syncthreads();
    if (tid < NW) {
        float t = 0.f;
#pragma unroll
        for (int k = 0; k < 8; k++) t += osum[tid * 8 + k];
        out[b * NW + tid] = t;
    }
}

extern "C" void kernel_launch(void* const* d_in, const int* in_sizes, int n_in,
                              void* d_out, int out_size)
{
    // Identify inputs by element count — robust to metadata ordering.
    const float* x = nullptr;      // 4096*256 = 1048576
    const float* W = nullptr;      // 12*256   = 3072
    const float* params = nullptr; // 4*12*1   = 48
    for (int i = 0; i < n_in; i++) {
        if      (in_sizes[i] == 4096 * 256) x      = (const float*)d_in[i];
        else if (in_sizes[i] == 12 * 256)   W      = (const float*)d_in[i];
        else if (in_sizes[i] == 48)         params = (const float*)d_in[i];
    }
    sim_kernel<<<4096, NT>>>(x, W, params, (float*)d_out);
}

// round 4
// speedup vs baseline: 1.0651x; 1.0651x over previous
#include <cuda_runtime.h>

#define NW 12
#define DIM 4096        // 2^12
#define INDIM 256
#define DEPTH 4
#define NT 256

// XOR swizzle so all three phase layouts are bank-conflict-free
__device__ __forceinline__ int slot(int i) { return i ^ ((i >> 4) & 0xF); }

// RX pair update: b0 = c*a0 - i s a1 ; b1 = -i s a0 + c*a1
__device__ __forceinline__ void rx_pair(float2& a0, float2& a1, float c, float s) {
    float b0x = fmaf(c, a0.x,  s * a1.y);
    float b0y = fmaf(c, a0.y, -s * a1.x);
    float b1x = fmaf(c, a1.x,  s * a0.y);
    float b1y = fmaf(c, a1.y, -s * a0.x);
    a0.x = b0x; a0.y = b0y; a1.x = b1x; a1.y = b1y;
}

// Apply RX butterflies on local bits [k0, 4) of A[16]
template<int K0>
__device__ __forceinline__ void applyK(float2 A[16], const float ck[4], const float sk[4]) {
#pragma unroll
    for (int k = K0; k < 4; k++) {
        const int m = 1 << k;
#pragma unroll
        for (int i0 = 0; i0 < 16; i0++)
            if (!(i0 & m)) rx_pair(A[i0], A[i0 | m], ck[k], sk[k]);
    }
}

__global__ void __launch_bounds__(NT)
sim_kernel(const float* __restrict__ x, const float* __restrict__ W,
           const float* __restrict__ params, float* __restrict__ out)
{
    __shared__ float2 st[DIM];              // 32 KB state
    __shared__ float ic[NW], isn[NW];       // merged initial-layer cos/sin (half-angle)
    __shared__ float pc[DEPTH * NW], ps[DEPTH * NW];   // d>=1 used
    __shared__ float red[NW * 8];
    __shared__ float prodlo[256];           // product over global bits 0..7 (wires 11..4)
    __shared__ float prodhi[16];            // product over global bits 8..11 (wires 3..0)
    __shared__ float osum[NW * 8];

    const int tid  = threadIdx.x;
    const int b    = blockIdx.x;
    const int lane = tid & 31;
    const int warp = tid >> 5;

    // ---- angles[b,w] = dot(x[b,:], W[w,:]) ----
    float xv = x[b * INDIM + tid];
#pragma unroll
    for (int w = 0; w < NW; w++) {
        float p = xv * __ldg(&W[w * INDIM + tid]);
#pragma unroll
        for (int o = 16; o > 0; o >>= 1) p += __shfl_xor_sync(0xffffffffu, p, o);
        if (lane == 0) red[w * 8 + warp] = p;
    }
    __syncthreads();
    if (tid < NW) {
        float a = 0.f;
#pragma unroll
        for (int k = 0; k < 8; k++) a += red[tid * 8 + k];
        // merge depth-0 RX into the initial layer (no CNOT in between);
        // wire 11 is target-only, its RX commutes through every chain: merge all depths
        float th = a + params[tid];
        if (tid == 11) th += params[NW + 11] + params[2 * NW + 11] + params[3 * NW + 11];
        float sv, cv; sincosf(th * 0.5f, &sv, &cv);
        ic[tid] = cv; isn[tid] = sv;
    }
    if (tid < DEPTH * NW) {
        float sv, cv; sincosf(params[tid] * 0.5f, &sv, &cv);
        pc[tid] = cv; ps[tid] = sv;
    }
    __syncthreads();

    // ---- product tables: |amp(m)| = prodhi[m>>8] * prodlo[m & 255] ----
    {
        float v = 1.f;
#pragma unroll
        for (int bb = 0; bb < 8; bb++) v *= ((tid >> bb) & 1) ? isn[11 - bb] : ic[11 - bb];
        prodlo[tid] = v;
        if (tid < 16) {
            float u = 1.f;
#pragma unroll
            for (int bb = 0; bb < 4; bb++) u *= ((tid >> bb) & 1) ? isn[3 - bb] : ic[3 - bb];
            prodhi[tid] = u;
        }
    }
    __syncthreads();

    // ---- construct state AFTER the first CNOT chain, directly in the depth-1
    //      hi layout: A[g] holds index j=(g<<8)|tid, value = product_amp(j ^ (j>>1))
    float2 A[16];
#pragma unroll
    for (int g = 0; g < 16; g++) {
        int j = (g << 8) | tid;
        int m = j ^ (j >> 1);
        float mag = prodhi[m >> 8] * prodlo[m & 255];
        int c = __popc(m) & 3;          // amp = mag * (-i)^c
        float2 a;
        a.x = (c == 0) ? mag : ((c == 2) ? -mag : 0.f);
        a.y = (c == 1) ? -mag : ((c == 3) ? mag : 0.f);
        A[g] = a;
    }

    const int mid_base = ((tid >> 4) << 8) | (tid & 15);

    // ---- depths 1..3: hi (wires 0-3), mid (wires 4-7), lo (wires 8-10; wire 11 merged out)
    for (int d = 1; d < DEPTH; d++) {
        const float* pcd = pc + d * NW;
        const float* psd = ps + d * NW;

        if (d > 1) {
            // hi-phase read with CNOT-chain perm fused: new[j] = old[j ^ (j>>1)]
#pragma unroll
            for (int g = 0; g < 16; g++) {
                int j = (g << 8) | tid;
                A[g] = st[slot(j ^ (j >> 1))];
            }
            __syncthreads();   // all perm reads before any write
        }
        {   // hi: local bit k <-> wire 3-k
            float ck[4], sk[4];
#pragma unroll
            for (int k = 0; k < 4; k++) { ck[k] = pcd[3 - k]; sk[k] = psd[3 - k]; }
            applyK<0>(A, ck, sk);
        }
#pragma unroll
        for (int g = 0; g < 16; g++) st[slot((g << 8) | tid)] = A[g];
        __syncthreads();

        // mid: local bit k <-> wire 7-k
#pragma unroll
        for (int g = 0; g < 16; g++) A[g] = st[slot(mid_base | (g << 4))];
        {
            float ck[4], sk[4];
#pragma unroll
            for (int k = 0; k < 4; k++) { ck[k] = pcd[7 - k]; sk[k] = psd[7 - k]; }
            applyK<0>(A, ck, sk);
        }
#pragma unroll
        for (int g = 0; g < 16; g++) st[slot(mid_base | (g << 4))] = A[g];
        __syncthreads();

        // lo: local bit k <-> wire 11-k ; k=0 (wire 11) already merged out
#pragma unroll
        for (int g = 0; g < 16; g++) A[g] = st[slot((tid << 4) | g)];
        {
            float ck[4], sk[4];
#pragma unroll
            for (int k = 1; k < 4; k++) { ck[k] = pcd[11 - k]; sk[k] = psd[11 - k]; }
            ck[0] = 1.f; sk[0] = 0.f;
            applyK<1>(A, ck, sk);
        }
        if (d < DEPTH - 1) {
#pragma unroll
            for (int g = 0; g < 16; g++) st[slot((tid << 4) | g)] = A[g];
            __syncthreads();
        }
        // d == DEPTH-1: amplitudes stay in registers for measurement
    }

    // ---- per-wire measurement with final CNOT perm absorbed:
    // measured state F[m] = S[m ^ (m>>1)] => with j = gray(m):
    // out[w] = sum_j (1 - 2*parity(popc(j >> (11-w)))) * |S_j|^2
    float acc[NW];
#pragma unroll
    for (int w = 0; w < NW; w++) acc[w] = 0.f;

#pragma unroll
    for (int g = 0; g < 16; g++) {
        int j = (tid << 4) | g;
        float p = A[g].x * A[g].x + A[g].y * A[g].y;
        int par = 0;
#pragma unroll
        for (int bb = 11; bb >= 0; bb--) {
            par ^= (j >> bb) & 1;       // par = parity(popc(j >> bb))
            acc[11 - bb] += par ? -p : p;
        }
    }
#pragma unroll
    for (int w = 0; w < NW; w++) {
        float v = acc[w];
#pragma unroll
        for (int o = 16; o > 0; o >>= 1) v += __shfl_xor_sync(0xffffffffu, v, o);
        if (lane == 0) osum[w * 8 + warp] = v;
    }
    __syncthreads();
    if (tid < NW) {
        float t = 0.f;
#pragma unroll
        for (int k = 0; k < 8; k++) t += osum[tid * 8 + k];
        out[b * NW + tid] = t;
    }
}

extern "C" void kernel_launch(void* const* d_in, const int* in_sizes, int n_in,
                              void* d_out, int out_size)
{
    // Identify inputs by element count — robust to metadata ordering.
    const float* x = nullptr;      // 4096*256 = 1048576
    const float* W = nullptr;      // 12*256   = 3072
    const float* params = nullptr; // 4*12*1   = 48
    for (int i = 0; i < n_in; i++) {
        if      (in_sizes[i] == 4096 * 256) x      = (const float*)d_in[i];
        else if (in_sizes[i] == 12 * 256)   W      = (const float*)d_in[i];
        else if (in_sizes[i] == 48)         params = (const float*)d_in[i];
    }
    sim_kernel<<<4096, NT>>>(x, W, params, (float*)d_out);
}

// round 5
// speedup vs baseline: 1.2575x; 1.1807x over previous
#include <cuda_runtime.h>

#define NW 12
#define DIM 4096        // 2^12
#define INDIM 256
#define DEPTH 4
#define NT 256

// XOR swizzle so all three phase layouts are bank-conflict-free
__device__ __forceinline__ int slot(int i) { return i ^ ((i >> 4) & 0xF); }

// RX pair update: b0 = c*a0 - i s a1 ; b1 = -i s a0 + c*a1
__device__ __forceinline__ void rx_pair(float2& a0, float2& a1, float c, float s) {
    float b0x = fmaf(c, a0.x,  s * a1.y);
    float b0y = fmaf(c, a0.y, -s * a1.x);
    float b1x = fmaf(c, a1.x,  s * a0.y);
    float b1y = fmaf(c, a1.y, -s * a0.x);
    a0.x = b0x; a0.y = b0y; a1.x = b1x; a1.y = b1y;
}

// Apply RX butterflies on local bits [K0, 4) of A[16]
template<int K0>
__device__ __forceinline__ void applyK(float2 A[16], const float ck[4], const float sk[4]) {
#pragma unroll
    for (int k = K0; k < 4; k++) {
        const int m = 1 << k;
#pragma unroll
        for (int i0 = 0; i0 < 16; i0++)
            if (!(i0 & m)) rx_pair(A[i0], A[i0 | m], ck[k], sk[k]);
    }
}

__global__ void __launch_bounds__(NT, 3)
sim_kernel(const float* __restrict__ x, const float* __restrict__ W,
           const float* __restrict__ params, float* __restrict__ out)
{
    __shared__ float2 st[DIM];              // 32 KB state
    __shared__ float ic[NW], isn[NW];       // merged initial-layer cos/sin (half-angle)
    __shared__ float pc[DEPTH * NW], ps[DEPTH * NW];   // d>=1 used
    __shared__ float red[NW * 8];
    __shared__ float prodlo[256];           // product over global bits 0..7 (wires 11..4)
    __shared__ float prodhi[16];            // product over global bits 8..11 (wires 3..0)
    __shared__ float osum[NW * 8];

    const int tid  = threadIdx.x;
    const int b    = blockIdx.x;
    const int lane = tid & 31;
    const int warp = tid >> 5;

    // ---- angles[b,w] = dot(x[b,:], W[w,:]) ----
    float xv = x[b * INDIM + tid];
#pragma unroll
    for (int w = 0; w < NW; w++) {
        float p = xv * __ldg(&W[w * INDIM + tid]);
#pragma unroll
        for (int o = 16; o > 0; o >>= 1) p += __shfl_xor_sync(0xffffffffu, p, o);
        if (lane == 0) red[w * 8 + warp] = p;
    }
    __syncthreads();
    if (tid < NW) {
        float a = 0.f;
#pragma unroll
        for (int k = 0; k < 8; k++) a += red[tid * 8 + k];
        // merge depth-0 RX into the initial layer (no CNOT in between);
        // wire 11 is target-only, its RX commutes through every chain: merge all depths
        float th = a + params[tid];
        if (tid == 11) th += params[NW + 11] + params[2 * NW + 11] + params[3 * NW + 11];
        float sv, cv; sincosf(th * 0.5f, &sv, &cv);
        ic[tid] = cv; isn[tid] = sv;
    }
    if (tid < DEPTH * NW) {
        float sv, cv; sincosf(params[tid] * 0.5f, &sv, &cv);
        pc[tid] = cv; ps[tid] = sv;
    }
    __syncthreads();

    // ---- product tables: |amp(m)| = prodhi[m>>8] * prodlo[m & 255] ----
    {
        float v = 1.f;
#pragma unroll
        for (int bb = 0; bb < 8; bb++) v *= ((tid >> bb) & 1) ? isn[11 - bb] : ic[11 - bb];
        prodlo[tid] = v;
        if (tid < 16) {
            float u = 1.f;
#pragma unroll
            for (int bb = 0; bb < 4; bb++) u *= ((tid >> bb) & 1) ? isn[3 - bb] : ic[3 - bb];
            prodhi[tid] = u;
        }
    }
    __syncthreads();

    // ---- construct state AFTER the first CNOT chain, directly in the depth-1
    //      hi layout: A[g] holds index j=(g<<8)|tid, value = product_amp(j ^ (j>>1))
    float2 A[16];
#pragma unroll
    for (int g = 0; g < 16; g++) {
        int j = (g << 8) | tid;
        int m = j ^ (j >> 1);
        float mag = prodhi[m >> 8] * prodlo[m & 255];
        int c = __popc(m) & 3;          // amp = mag * (-i)^c
        float2 a;
        a.x = (c == 0) ? mag : ((c == 2) ? -mag : 0.f);
        a.y = (c == 1) ? -mag : ((c == 3) ? mag : 0.f);
        A[g] = a;
    }

    const int mid_base = ((tid >> 4) << 8) | (tid & 15);

    // ---- depths 1..3: hi (wires 0-3), mid (wires 4-7), lo (wires 8-10; wire 11 merged out)
    for (int d = 1; d < DEPTH; d++) {
        const float* pcd = pc + d * NW;
        const float* psd = ps + d * NW;

        if (d > 1) {
            // hi-phase read with CNOT-chain perm fused: new[j] = old[j ^ (j>>1)]
#pragma unroll
            for (int g = 0; g < 16; g++) {
                int j = (g << 8) | tid;
                A[g] = st[slot(j ^ (j >> 1))];
            }
            __syncthreads();   // all perm reads before any write
        }
        {   // hi: local bit k <-> wire 3-k
            float ck[4], sk[4];
#pragma unroll
            for (int k = 0; k < 4; k++) { ck[k] = pcd[3 - k]; sk[k] = psd[3 - k]; }
            applyK<0>(A, ck, sk);
        }
#pragma unroll
        for (int g = 0; g < 16; g++) st[slot((g << 8) | tid)] = A[g];
        __syncthreads();

        // mid: local bit k <-> wire 7-k
#pragma unroll
        for (int g = 0; g < 16; g++) A[g] = st[slot(mid_base | (g << 4))];
        {
            float ck[4], sk[4];
#pragma unroll
            for (int k = 0; k < 4; k++) { ck[k] = pcd[7 - k]; sk[k] = psd[7 - k]; }
            applyK<0>(A, ck, sk);
        }
#pragma unroll
        for (int g = 0; g < 16; g++) st[slot(mid_base | (g << 4))] = A[g];
        __syncthreads();

        // lo: local bit k <-> wire 11-k ; k=0 (wire 11) already merged out
#pragma unroll
        for (int g = 0; g < 16; g++) A[g] = st[slot((tid << 4) | g)];
        {
            float ck[4], sk[4];
#pragma unroll
            for (int k = 1; k < 4; k++) { ck[k] = pcd[11 - k]; sk[k] = psd[11 - k]; }
            ck[0] = 1.f; sk[0] = 0.f;
            applyK<1>(A, ck, sk);
        }
        if (d < DEPTH - 1) {
#pragma unroll
            for (int g = 0; g < 16; g++) st[slot((tid << 4) | g)] = A[g];
            __syncthreads();
        }
        // d == DEPTH-1: amplitudes stay in registers for measurement
    }

    // ---- collapse amplitudes to magnitudes first (kills A's 32 regs before acc[12] lives)
    float p[16];
#pragma unroll
    for (int g = 0; g < 16; g++)
        p[g] = fmaf(A[g].x, A[g].x, A[g].y * A[g].y);

    // ---- per-wire measurement with final CNOT perm absorbed:
    // measured state F[m] = S[m ^ (m>>1)] => with j = gray(m):
    // out[w] = sum_j (1 - 2*parity(popc(j >> (11-w)))) * |S_j|^2
    float acc[NW];
#pragma unroll
    for (int w = 0; w < NW; w++) acc[w] = 0.f;

#pragma unroll
    for (int g = 0; g < 16; g++) {
        int j = (tid << 4) | g;
        int par = 0;
#pragma unroll
        for (int bb = 11; bb >= 0; bb--) {
            par ^= (j >> bb) & 1;       // par = parity(popc(j >> bb))
            acc[11 - bb] += par ? -p[g] : p[g];
        }
    }
#pragma unroll
    for (int w = 0; w < NW; w++) {
        float v = acc[w];
#pragma unroll
        for (int o = 16; o > 0; o >>= 1) v += __shfl_xor_sync(0xffffffffu, v, o);
        if (lane == 0) osum[w * 8 + warp] = v;
    }
    __syncthreads();
    if (tid < NW) {
        float t = 0.f;
#pragma unroll
        for (int k = 0; k < 8; k++) t += osum[tid * 8 + k];
        out[b * NW + tid] = t;
    }
}

extern "C" void kernel_launch(void* const* d_in, const int* in_sizes, int n_in,
                              void* d_out, int out_size)
{
    // Identify inputs by element count — robust to metadata ordering.
    const float* x = nullptr;      // 4096*256 = 1048576
    const float* W = nullptr;      // 12*256   = 3072
    const float* params = nullptr; // 4*12*1   = 48
    for (int i = 0; i < n_in; i++) {
        if      (in_sizes[i] == 4096 * 256) x      = (const float*)d_in[i];
        else if (in_sizes[i] == 12 * 256)   W      = (const float*)d_in[i];
        else if (in_sizes[i] == 48)         params = (const float*)d_in[i];
    }
    sim_kernel<<<4096, NT>>>(x, W, params, (float*)d_out);
}

// round 6
// speedup vs baseline: 1.3472x; 1.0713x over previous
#include <cuda_runtime.h>

#define NW 12
#define DIM 4096        // 2^12
#define INDIM 256
#define DEPTH 4
#define NT 256

// XOR swizzle so all three phase layouts are bank-conflict-free
__device__ __forceinline__ int slot(int i) { return i ^ ((i >> 4) & 0xF); }

// RX pair update: b0 = c*a0 - i s a1 ; b1 = -i s a0 + c*a1
__device__ __forceinline__ void rx_pair(float2& a0, float2& a1, float c, float s) {
    float b0x = fmaf(c, a0.x,  s * a1.y);
    float b0y = fmaf(c, a0.y, -s * a1.x);
    float b1x = fmaf(c, a1.x,  s * a0.y);
    float b1y = fmaf(c, a1.y, -s * a0.x);
    a0.x = b0x; a0.y = b0y; a1.x = b1x; a1.y = b1y;
}

// Apply RX butterflies on local bits [K0, 4) of A[16]
template<int K0>
__device__ __forceinline__ void applyK(float2 A[16], const float ck[4], const float sk[4]) {
#pragma unroll
    for (int k = K0; k < 4; k++) {
        const int m = 1 << k;
#pragma unroll
        for (int i0 = 0; i0 < 16; i0++)
            if (!(i0 & m)) rx_pair(A[i0], A[i0 | m], ck[k], sk[k]);
    }
}

__global__ void __launch_bounds__(NT, 4)
sim_kernel(const float* __restrict__ x, const float* __restrict__ W,
           const float* __restrict__ params, float* __restrict__ out)
{
    __shared__ float2 st[DIM];              // 32 KB state
    __shared__ float ic[NW], isn[NW];       // merged initial-layer cos/sin (half-angle)
    __shared__ float pc[DEPTH * NW], ps[DEPTH * NW];   // d>=1 used
    __shared__ float red[NW * 8];
    __shared__ float prodlo[256];           // product over global bits 0..7 (wires 11..4)
    __shared__ float prodhi[16];            // product over global bits 8..11 (wires 3..0)
    __shared__ float osum[NW * 8];

    const int tid  = threadIdx.x;
    const int b    = blockIdx.x;
    const int lane = tid & 31;
    const int warp = tid >> 5;

    // ---- angles[b,w] = dot(x[b,:], W[w,:]) ----
    float xv = x[b * INDIM + tid];
#pragma unroll
    for (int w = 0; w < NW; w++) {
        float p = xv * __ldg(&W[w * INDIM + tid]);
#pragma unroll
        for (int o = 16; o > 0; o >>= 1) p += __shfl_xor_sync(0xffffffffu, p, o);
        if (lane == 0) red[w * 8 + warp] = p;
    }
    __syncthreads();
    if (tid < NW) {
        float a = 0.f;
#pragma unroll
        for (int k = 0; k < 8; k++) a += red[tid * 8 + k];
        // merge depth-0 RX into the initial layer (no CNOT in between);
        // wire 11 is target-only, its RX commutes through every chain: merge all depths
        float th = a + params[tid];
        if (tid == 11) th += params[NW + 11] + params[2 * NW + 11] + params[3 * NW + 11];
        float sv, cv; sincosf(th * 0.5f, &sv, &cv);
        ic[tid] = cv; isn[tid] = sv;
    }
    if (tid < DEPTH * NW) {
        float sv, cv; sincosf(params[tid] * 0.5f, &sv, &cv);
        pc[tid] = cv; ps[tid] = sv;
    }
    __syncthreads();

    // ---- product tables: |amp(m)| = prodhi[m>>8] * prodlo[m & 255] ----
    {
        float v = 1.f;
#pragma unroll
        for (int bb = 0; bb < 8; bb++) v *= ((tid >> bb) & 1) ? isn[11 - bb] : ic[11 - bb];
        prodlo[tid] = v;
        if (tid < 16) {
            float u = 1.f;
#pragma unroll
            for (int bb = 0; bb < 4; bb++) u *= ((tid >> bb) & 1) ? isn[3 - bb] : ic[3 - bb];
            prodhi[tid] = u;
        }
    }
    __syncthreads();

    // ---- construct state AFTER the first CNOT chain, directly in the depth-1
    //      hi layout: A[g] holds index j=(g<<8)|tid, value = product_amp(j ^ (j>>1))
    float2 A[16];
#pragma unroll
    for (int g = 0; g < 16; g++) {
        int j = (g << 8) | tid;
        int m = j ^ (j >> 1);
        float mag = prodhi[m >> 8] * prodlo[m & 255];
        int c = __popc(m) & 3;          // amp = mag * (-i)^c
        float2 a;
        a.x = (c == 0) ? mag : ((c == 2) ? -mag : 0.f);
        a.y = (c == 1) ? -mag : ((c == 3) ? mag : 0.f);
        A[g] = a;
    }

    const int mid_base = ((tid >> 4) << 8) | (tid & 15);

    // ---- depths 1..3: hi (wires 0-3), mid (wires 4-7), lo (wires 8-10; wire 11 merged out)
    for (int d = 1; d < DEPTH; d++) {
        const float* pcd = pc + d * NW;
        const float* psd = ps + d * NW;

        if (d > 1) {
            // hi-phase read with CNOT-chain perm fused: new[j] = old[j ^ (j>>1)]
#pragma unroll
            for (int g = 0; g < 16; g++) {
                int j = (g << 8) | tid;
                A[g] = st[slot(j ^ (j >> 1))];
            }
            __syncthreads();   // all perm reads before any write
        }
        {   // hi: local bit k <-> wire 3-k
            float ck[4], sk[4];
#pragma unroll
            for (int k = 0; k < 4; k++) { ck[k] = pcd[3 - k]; sk[k] = psd[3 - k]; }
            applyK<0>(A, ck, sk);
        }
#pragma unroll
        for (int g = 0; g < 16; g++) st[slot((g << 8) | tid)] = A[g];
        __syncthreads();

        // mid: local bit k <-> wire 7-k
#pragma unroll
        for (int g = 0; g < 16; g++) A[g] = st[slot(mid_base | (g << 4))];
        {
            float ck[4], sk[4];
#pragma unroll
            for (int k = 0; k < 4; k++) { ck[k] = pcd[7 - k]; sk[k] = psd[7 - k]; }
            applyK<0>(A, ck, sk);
        }
#pragma unroll
        for (int g = 0; g < 16; g++) st[slot(mid_base | (g << 4))] = A[g];
        __syncthreads();

        // lo: local bit k <-> wire 11-k ; k=0 (wire 11) already merged out
#pragma unroll
        for (int g = 0; g < 16; g++) A[g] = st[slot((tid << 4) | g)];
        {
            float ck[4], sk[4];
#pragma unroll
            for (int k = 1; k < 4; k++) { ck[k] = pcd[11 - k]; sk[k] = psd[11 - k]; }
            ck[0] = 1.f; sk[0] = 0.f;
            applyK<1>(A, ck, sk);
        }
        if (d < DEPTH - 1) {
#pragma unroll
            for (int g = 0; g < 16; g++) st[slot((tid << 4) | g)] = A[g];
            __syncthreads();
        }
        // d == DEPTH-1: amplitudes stay in registers for measurement
    }

    // ---- factorized per-wire measurement (final CNOT perm absorbed):
    // j = (tid<<4)|g.  For wires 0..7 (bb=11..4): sign depends only on tid -> +-psum.
    // For wires 8..11 (bb=3..0): sign = parity(popc(tid)) ^ parity(popc(g>>bb));
    // the g-part is compile-time -> pure add/sub chains T3..T0.
    float p[16];
#pragma unroll
    for (int g = 0; g < 16; g++)
        p[g] = fmaf(A[g].x, A[g].x, A[g].y * A[g].y);

    float psum = 0.f, T3 = 0.f, T2 = 0.f, T1 = 0.f, T0 = 0.f;
#pragma unroll
    for (int g = 0; g < 16; g++) {
        const int g3 = (g >> 3) & 1, g2 = (g >> 2) & 1, g1 = (g >> 1) & 1, g0 = g & 1;
        float v = p[g];
        psum += v;
        T3 += (g3) ? -v : v;                       // bb=3 (wire 8)
        T2 += (g3 ^ g2) ? -v : v;                  // bb=2 (wire 9)
        T1 += (g3 ^ g2 ^ g1) ? -v : v;             // bb=1 (wire 10)
        T0 += (g3 ^ g2 ^ g1 ^ g0) ? -v : v;        // bb=0 (wire 11)
    }

    // per-thread sign bits: wire w (0..7): parity(popc(tid >> (7-w)))
    int pm = 0;
    {
        int par = 0;
#pragma unroll
        for (int w = 0; w < 8; w++) { par ^= (tid >> (7 - w)) & 1; pm |= par << w; }
    }
    const int parT = __popc(tid) & 1;

    float vals[NW];
#pragma unroll
    for (int w = 0; w < 8; w++) vals[w] = ((pm >> w) & 1) ? -psum : psum;
    vals[8]  = parT ? -T3 : T3;
    vals[9]  = parT ? -T2 : T2;
    vals[10] = parT ? -T1 : T1;
    vals[11] = parT ? -T0 : T0;

#pragma unroll
    for (int w = 0; w < NW; w++) {
        float v = vals[w];
#pragma unroll
        for (int o = 16; o > 0; o >>= 1) v += __shfl_xor_sync(0xffffffffu, v, o);
        if (lane == 0) osum[w * 8 + warp] = v;
    }
    __syncthreads();
    if (tid < NW) {
        float t = 0.f;
#pragma unroll
        for (int k = 0; k < 8; k++) t += osum[tid * 8 + k];
        out[b * NW + tid] = t;
    }
}

extern "C" void kernel_launch(void* const* d_in, const int* in_sizes, int n_in,
                              void* d_out, int out_size)
{
    // Identify inputs by element count — robust to metadata ordering.
    const float* x = nullptr;      // 4096*256 = 1048576
    const float* W = nullptr;      // 12*256   = 3072
    const float* params = nullptr; // 4*12*1   = 48
    for (int i = 0; i < n_in; i++) {
        if      (in_sizes[i] == 4096 * 256) x      = (const float*)d_in[i];
        else if (in_sizes[i] == 12 * 256)   W      = (const float*)d_in[i];
        else if (in_sizes[i] == 48)         params = (const float*)d_in[i];
    }
    sim_kernel<<<4096, NT>>>(x, W, params, (float*)d_out);
}